// round 13
// baseline (speedup 1.0000x reference)
#include <cuda_runtime.h>

// Problem constants (fixed by the reference: B=2048, S=128, N=B*S).
#define B_ROWS   2048
#define S_ITEMS  128
#define WARPS_PB 8                       // warps per block (1 row per warp)
#define NBLOCKS  (B_ROWS / WARPS_PB)     // 256 blocks

// Scratch (no device allocation allowed -> __device__ globals).
__device__ float g_partial[NBLOCKS];

// Analytic simplification of the reference (valid because y is one-hot per
// assortment row, which setup_inputs guarantees):
//   result = (1/B) * sum_b [ s_b + log(S - rank_b) ]
// where
//   chosen_b = xa at the one-hot position,
//   s_b      = sum_k relu(xa[b,k] - chosen_b),
//   rank_b   = stable ascending rank of chosen within the row
//            = #{k: xa<chosen} + #{k<pos: xa==chosen}.
//
// Measured evidence driving this structure:
//  * Fused single-kernel versions all ran >= 7.17us regardless of tail style
//    (atomic fold, fence+tree, spread tickets): the in-kernel completion
//    chain (straggler spread x contended single-address atomics + read-back)
//    costs ~3us.
//  * The identical gather with a PLAIN STORE tail measured ~4us (R2).
//  * Graph-sequential kernel-to-kernel overhead measured ~0.1-0.3us.
// => split: kernel A (gather -> 256 block partials, plain store) + kernel B
//    (tiny parallel tree reduce). Cross-kernel visibility is guaranteed by
//    stream/graph ordering; no fences or atomics anywhere.

__global__ void __launch_bounds__(256) exp_loss_gather(
    const float* __restrict__ x,
    const float* __restrict__ y,
    const int*   __restrict__ assort)
{
    const unsigned FULL = 0xffffffffu;
    const int tid    = threadIdx.x;
    const int lane   = tid & 31;
    const int warpid = tid >> 5;                        // 0..7
    const int row    = blockIdx.x * WARPS_PB + warpid;  // 0..2047

    // ---- per-row: 1 int4 index load + 8 independent gathers, batched ----
    const int4* arow = reinterpret_cast<const int4*>(assort + row * S_ITEMS);
    int4 a = __ldg(arow + lane);
    int idx4[4] = {a.x, a.y, a.z, a.w};

    float xv[4], yv[4];
#pragma unroll
    for (int i = 0; i < 4; i++) {
        xv[i] = __ldg(x + idx4[i]);
        yv[i] = __ldg(y + idx4[i]);
    }

    // Locate the one-hot item: one ballot + 2 shfl broadcasts.
    float lch  = 0.0f;
    int   lpos = -1;
#pragma unroll
    for (int i = 0; i < 4; i++) {
        lch += xv[i] * yv[i];              // exact: other terms are +-0
        if (yv[i] != 0.0f) lpos = lane * 4 + i;
    }
    unsigned bal = __ballot_sync(FULL, lpos >= 0);
    int   src = __ffs(bal) - 1;            // exactly one lane holds the item
    float ch  = __shfl_sync(FULL, lch,  src);
    int   pos = __shfl_sync(FULL, lpos, src);

    // s = sum relu(xa - chosen);  rank = stable ascending rank of chosen.
    float sv = 0.0f;
    int   rk = 0;
#pragma unroll
    for (int i = 0; i < 4; i++) {
        sv += fmaxf(xv[i] - ch, 0.0f);
        int gi = lane * 4 + i;
        rk += (xv[i] < ch) || (xv[i] == ch && gi < pos);
    }
#pragma unroll
    for (int o = 16; o; o >>= 1)
        sv += __shfl_xor_sync(FULL, sv, o);
    rk = __reduce_add_sync(FULL, rk);      // REDUX.SUM

    // ---- block fold: 8 warp values -> one float partial, plain store ----
    __shared__ float warpval[WARPS_PB];
    if (lane == 0)
        warpval[warpid] = sv + __logf((float)(S_ITEMS - rk));
    __syncthreads();

    if (tid == 0) {
        double acc = 0.0;
#pragma unroll
        for (int i = 0; i < WARPS_PB; i++) acc += (double)warpval[i];
        g_partial[blockIdx.x] = (float)acc;   // visibility via graph ordering
    }
}

// Tiny parallel reduce: 256 partials, one coalesced load per thread (all in
// flight simultaneously), fixed-order shfl + smem tree -> deterministic.
__global__ void __launch_bounds__(256) exp_loss_reduce(float* __restrict__ out)
{
    const unsigned FULL = 0xffffffffu;
    const int tid  = threadIdx.x;
    const int lane = tid & 31;
    const int wid  = tid >> 5;

    double v = (double)g_partial[tid];     // 256 parallel loads (8 sectors)
#pragma unroll
    for (int o = 16; o; o >>= 1)
        v += __shfl_xor_sync(FULL, v, o);

    __shared__ double wsum[8];
    if (lane == 0) wsum[wid] = v;
    __syncthreads();

    if (tid == 0) {
        double acc = 0.0;
#pragma unroll
        for (int i = 0; i < 8; i++) acc += wsum[i];
        out[0] = (float)(acc / (double)B_ROWS);
    }
}

extern "C" void kernel_launch(void* const* d_in, const int* in_sizes, int n_in,
                              void* d_out, int out_size)
{
    const float* x      = (const float*)d_in[0];
    const float* y      = (const float*)d_in[1];
    const int*   assort = (const int*)d_in[2];

    exp_loss_gather<<<NBLOCKS, 256>>>(x, y, assort);
    exp_loss_reduce<<<1, 256>>>((float*)d_out);
}

// round 14
// speedup vs baseline: 1.2250x; 1.2250x over previous
#include <cuda_runtime.h>

// Problem constants (fixed by the reference: B=2048, S=128, N=B*S).
#define B_ROWS   2048
#define S_ITEMS  128
#define WARPS_PB 8                       // warps per block (1 row per warp)
#define NBLOCKS  (B_ROWS / WARPS_PB)     // 256 blocks
#define FX_SCALE 1048576.0               // 2^20 fixed-point scale

// Scratch (no device allocation allowed -> __device__ global, zero-init).
// Layout: bits [0,48)  = fixed-point sum of block partials (all non-negative)
//         bits [48,64) = number of blocks that have contributed
__device__ unsigned long long g_acc;

// Analytic simplification of the reference (valid because y is one-hot per
// assortment row, which setup_inputs guarantees):
//   result = (1/B) * sum_b [ s_b + log(S - rank_b) ]
// where
//   chosen_b = xa at the one-hot position,
//   s_b      = sum_k relu(xa[b,k] - chosen_b),
//   rank_b   = stable ascending rank of chosen within the row
//            = #{k: xa<chosen} + #{k<pos: xa==chosen}.
//
// Measured evidence driving this structure:
//  * Any second kernel costs ~4.9us (grid=1 reduce floor) -> single launch.
//  * Gather with plain-store tail ~4.6us; fused with TWO same-address atomic
//    streams (value + ticket) 7.17us -> the 2x256 serialized L2 atomics cost
//    ~2.6us (~27cyc/op single-address serialization).
// => ONE packed 64-bit atomicAdd per block: low 48 bits = 2^20 fixed-point
//    value (every partial >= 0), high 16 bits = block count. The returned old
//    value IS both the ticket and the running sum -> last block computes the
//    total with no read-back. Integer adds commute -> bit-deterministic.
__global__ void __launch_bounds__(256) exp_loss_fused(
    const float* __restrict__ x,
    const float* __restrict__ y,
    const int*   __restrict__ assort,
    float*       __restrict__ out)
{
    const unsigned FULL = 0xffffffffu;
    const int tid    = threadIdx.x;
    const int lane   = tid & 31;
    const int warpid = tid >> 5;                        // 0..7
    const int row    = blockIdx.x * WARPS_PB + warpid;  // 0..2047

    // ---- per-row: 1 int4 index load + 8 independent gathers, batched ----
    const int4* arow = reinterpret_cast<const int4*>(assort + row * S_ITEMS);
    int4 a = __ldg(arow + lane);
    int idx4[4] = {a.x, a.y, a.z, a.w};

    float xv[4], yv[4];
#pragma unroll
    for (int i = 0; i < 4; i++) {
        xv[i] = __ldg(x + idx4[i]);
        yv[i] = __ldg(y + idx4[i]);
    }

    // Locate the one-hot item: one ballot + 2 shfl broadcasts.
    float lch  = 0.0f;
    int   lpos = -1;
#pragma unroll
    for (int i = 0; i < 4; i++) {
        lch += xv[i] * yv[i];              // exact: other terms are +-0
        if (yv[i] != 0.0f) lpos = lane * 4 + i;
    }
    unsigned bal = __ballot_sync(FULL, lpos >= 0);
    int   src = __ffs(bal) - 1;            // exactly one lane holds the item
    float ch  = __shfl_sync(FULL, lch,  src);
    int   pos = __shfl_sync(FULL, lpos, src);

    // s = sum relu(xa - chosen);  rank = stable ascending rank of chosen.
    float sv = 0.0f;
    int   rk = 0;
#pragma unroll
    for (int i = 0; i < 4; i++) {
        sv += fmaxf(xv[i] - ch, 0.0f);
        int gi = lane * 4 + i;
        rk += (xv[i] < ch) || (xv[i] == ch && gi < pos);
    }
#pragma unroll
    for (int o = 16; o; o >>= 1)
        sv += __shfl_xor_sync(FULL, sv, o);
    rk = __reduce_add_sync(FULL, rk);      // REDUX.SUM

    // ---- block fold: 8 warp values -> ONE packed atomic ----
    __shared__ float warpval[WARPS_PB];
    if (lane == 0)
        warpval[warpid] = sv + __logf((float)(S_ITEMS - rk));
    __syncthreads();

    if (tid == 0) {
        double acc = 0.0;
#pragma unroll
        for (int i = 0; i < WARPS_PB; i++) acc += (double)warpval[i];
        // acc >= 0 always (s >= 0, log(S-rank) >= log(1) = 0).
        unsigned long long fx = (unsigned long long)llrint(acc * FX_SCALE);
        unsigned long long packed = fx | (1ull << 48);
        unsigned long long old = atomicAdd(&g_acc, packed);
        if ((old >> 48) == (unsigned long long)(NBLOCKS - 1)) {
            // Last contributor: old's low bits already hold everyone else's
            // sum; add our own -> total. No read-back, no second atomic.
            unsigned long long total = (old & 0xFFFFFFFFFFFFull) + fx;
            out[0] = (float)((double)total / FX_SCALE / (double)B_ROWS);
            g_acc = 0ull;                  // reset for next graph replay
        }
    }
}

extern "C" void kernel_launch(void* const* d_in, const int* in_sizes, int n_in,
                              void* d_out, int out_size)
{
    const float* x      = (const float*)d_in[0];
    const float* y      = (const float*)d_in[1];
    const int*   assort = (const int*)d_in[2];

    exp_loss_fused<<<NBLOCKS, 256>>>(x, y, assort, (float*)d_out);
}